// round 17
// baseline (speedup 1.0000x reference)
#include <cuda_runtime.h>

// ISTSimulator: B=65536, V=2, L=200 per-lane recurrence.
// Round 17: warp-autonomous staging. Each warp transposes its own 32 lanes in
// a private smem tile; __syncwarp only (NO __syncthreads) -> no cross-warp
// pacing, no BAR cost. Math identical to R16: Taylor-propagated D (rcp reseed
// /8), geometric sigmoid F (exact reseed /16), warp votes, FFMA.SAT.

#define LOG2E_F 1.4426950408889634f
#define BT 128                         // threads per block (4 warps)

__device__ __forceinline__ float ex2a(float x) {
    float r; asm("ex2.approx.ftz.f32 %0, %1;" : "=f"(r) : "f"(x)); return r;
}
__device__ __forceinline__ float lg2a(float x) {
    float r; asm("lg2.approx.f32 %0, %1;" : "=f"(r) : "f"(x)); return r;
}
__device__ __forceinline__ float rcpa(float x) {
    float r; asm("rcp.approx.ftz.f32 %0, %1;" : "=f"(r) : "f"(x)); return r;
}

struct LS {
    float u, F;
    float lam, nlam, beta, nbeta, c2;
    float kd, nkd, kf, mu;
    float na, z0, c;
};

__device__ __forceinline__ void ls_init(LS& s, const float* p) {
    s.lam  = 0.001f * fmaxf(p[0], 0.0f);
    s.nlam = -s.lam;
    s.beta = fmaf(10.0f, fmaxf(p[1], 0.0f), 1.0f);
    s.nbeta = -s.beta;
    s.c2   = 0.5f * s.beta * (s.beta - 1.0f);
    s.kd   = p[2];
    s.nkd  = -s.kd;
    s.mu   = p[3];
    s.kf   = p[4];
    float a = LOG2E_F / p[6];
    s.z0 = p[5] * a;
    s.na = -a;
    s.c  = ex2a(s.na);
    s.u  = 1.0f;                       // u = 1 - D; stays in (0.38, 1]
    s.F  = 1e-12f;
}

// Process LEN steps (LEN in {8,16}) from absolute step n0g; stage float4s
// into smrow[(ofs4 + k) ^ swz].
template <int LEN>
__device__ __forceinline__ void grp(LS& s, bool cheap_all, float4* smrow,
                                    int swz, int ofs4, int n0g)
{
    float zs = fmaf((float)n0g, s.na, s.z0);         // exact group-start z
    float ze = fmaf((float)LEN, s.na, zs);
    // hazard: e pinned at reseed (inf/FTZ-0) while true g crosses back within
    // the group (z monotone -> predicate exact). Benign saturation stays cheap.
    bool pc = (zs >  126.0f && ze <  26.0f) ||
              (zs < -126.0f && ze > -26.0f);
    bool cheap = cheap_all && !__any_sync(0xffffffffu, pc);

    float4 v;
    if (cheap) {
        // exact reseed: d = lam*u^beta (MUFU, amortized /LEN)
        float l  = lg2a(s.u);
        float pw = ex2a(s.beta * l);
        float d  = s.lam * pw;
        float e  = ex2a(zs);
        #pragma unroll
        for (int h = 0; h < LEN / 8; ++h) {
            float r = rcpa(s.u);                     // r reseed per 8 steps
            #pragma unroll
            for (int jj = 0; jj < 8; ++jj) {
                float g = rcpa(1.0f + e);
                e *= s.c;
                float q = fmaf(s.mu, s.F, 1e-12f);
                s.F = __saturatef(fmaf(g, q, s.F));  // FFMA.SAT
                float x  = d * r;
                s.u -= d;
                float tt = fmaf(s.c2, x, s.nbeta);
                d *= fmaf(tt, x, 1.0f);              // d *= (1 - b*x + c2*x^2)
                float val = fmaf(s.kf, s.F, fmaf(s.nkd, s.u, s.kd));
                if ((jj & 3) == 0) v.x = val;
                else if ((jj & 3) == 1) v.y = val;
                else if ((jj & 3) == 2) v.z = val;
                else {
                    v.w = val;
                    smrow[(ofs4 + ((h * 8 + jj) >> 2)) ^ swz] = v;
                }
            }
        }
    } else {
        // exact path: per-step lg2/ex2 pow + saturating ex2 sigmoid
        #pragma unroll
        for (int jj = 0; jj < LEN; ++jj) {
            float l  = lg2a(s.u);
            float pw = ex2a(s.beta * l);
            s.u = fmaf(s.nlam, pw, s.u);
            float z = fmaf((float)jj, s.na, zs);
            float e = ex2a(z);                       // saturates safely
            float g = rcpa(1.0f + e);
            float q = fmaf(s.mu, s.F, 1e-12f);
            s.F = __saturatef(fmaf(g, q, s.F));
            float val = fmaf(s.kf, s.F, fmaf(s.nkd, s.u, s.kd));
            if ((jj & 3) == 0) v.x = val;
            else if ((jj & 3) == 1) v.y = val;
            else if ((jj & 3) == 2) v.z = val;
            else {
                v.w = val;
                smrow[(ofs4 + (jj >> 2)) ^ swz] = v;
            }
        }
    }
}

__global__ void __launch_bounds__(BT) ist_kernel(
    const float* __restrict__ in, float* __restrict__ out)
{
    __shared__ float4 sm4[BT * 8];     // 16 KB; warp w owns rows [w*32, w*32+32)
    int t   = threadIdx.x;
    int lid = t & 31;
    int base_lane = blockIdx.x * BT;

    LS s;
    ls_init(s, in + (size_t)(base_lane + t) * 7);
    bool cheap_all = __all_sync(0xffffffffu,
        (s.beta * s.lam < 0.05f) && (fabsf(s.na) < 126.0f));

    float4* smrow = &sm4[t * 8];       // this thread's staging row
    const int swz = lid & 7;           // XOR swizzle key (write side)

    // warp-local flush constants: lane handles rows r = it*4 + (lid>>3),
    // col group c4 = lid&7. warp_row0 = (t & ~31).
    float4* warp_tile = &sm4[(t & ~31) * 8];
    const int r_loc = lid >> 3;        // 0..3
    const int c4    = lid & 7;         // 0..7
    float* gbase = out + (size_t)(base_lane + (t & ~31)) * 200;

    #pragma unroll 1
    for (int chunk = 0; chunk < 7; ++chunk) {
        int n0 = chunk * 32;
        bool full = (chunk < 6);       // 200 = 6*32 + 8

        if (full) {
            grp<16>(s, cheap_all, smrow, swz, 0, n0);
            grp<16>(s, cheap_all, smrow, swz, 4, n0 + 16);
        } else {
            grp<8>(s, cheap_all, smrow, swz, 0, n0);
        }
        __syncwarp();

        if (full) {
            // 32 rows x 8 float4 per warp; 8 per lane. Phase lanes share a
            // row with all-distinct c4 ^ (r&7) -> conflict-free LDS.128;
            // 8 lanes/row -> full 128B STG lines.
            #pragma unroll
            for (int it = 0; it < 8; ++it) {
                int r = it * 4 + r_loc;            // 0..31
                float4 vv = warp_tile[r * 8 + (c4 ^ (r & 7))];
                *reinterpret_cast<float4*>(
                    &gbase[(size_t)r * 200 + n0 + c4 * 4]) = vv;
            }
        } else {
            // 32 rows x 2 float4 per warp; 2 per lane (4% of traffic)
            #pragma unroll
            for (int it = 0; it < 2; ++it) {
                int r  = it * 16 + (lid >> 1);     // 0..31
                int cc = lid & 1;
                float4 vv = warp_tile[r * 8 + (cc ^ (r & 7))];
                *reinterpret_cast<float4*>(
                    &gbase[(size_t)r * 200 + n0 + cc * 4]) = vv;
            }
        }
        if (chunk < 6) __syncwarp();
    }
}

// generic fallback for unexpected shapes
__global__ void __launch_bounds__(256) ist_generic(
    const float* __restrict__ in, float* __restrict__ out, int n_lanes)
{
    int tid = blockIdx.x * blockDim.x + threadIdx.x;
    if (tid >= n_lanes) return;
    const float* p = in + (size_t)tid * 7;
    float lam  = 0.001f * fmaxf(p[0], 0.0f);
    float beta = fmaf(10.0f, fmaxf(p[1], 0.0f), 1.0f);
    float kd = p[2], mu = p[3], kf = p[4];
    float a = LOG2E_F / p[6], z0 = p[5] * a;
    float u = 1.0f, F = 1e-12f, nf = 0.0f;
    float* o = out + (size_t)tid * 200;
    for (int n = 0; n < 200; ++n) {
        float l  = lg2a(fmaxf(u, 1e-12f));
        float pw = ex2a(beta * l);
        u = fminf(fmaxf(fmaf(-lam, pw, u), 0.0f), 1.0f);
        float z = fmaf(-nf, a, z0);
        float g = rcpa(1.0f + ex2a(z));
        float q = fmaf(mu, F, 1e-12f);
        F = __saturatef(fmaf(g, q, F));
        o[n] = fmaf(kf, F, fmaf(-kd, u, kd));
        nf += 1.0f;
    }
}

extern "C" void kernel_launch(void* const* d_in, const int* in_sizes, int n_in,
                              void* d_out, int out_size)
{
    const float* in = (const float*)d_in[0];
    float* out = (float*)d_out;
    int n_lanes = in_sizes[0] / 7;
    if (n_lanes % BT == 0) {
        ist_kernel<<<n_lanes / BT, BT>>>(in, out);
    } else {
        ist_generic<<<(n_lanes + 255) / 256, 256>>>(in, out, n_lanes);
    }
}